// round 9
// baseline (speedup 1.0000x reference)
#include <cuda_runtime.h>
#include <cstdint>

#define CHUNK 1024          // floats per early-exit quantum (4 KB)
#define NSUB  8             // sub-blocks of 128 floats (one float4 per lane)

__device__ int g_row_counter;

__global__ void reset_counter_kernel() { g_row_counter = 0; }

// ---------------------------------------------------------------------------
// Warp-autonomous bidirectional inverse-CDF sampler, branch-free hot path.
//   sample = #{v : r > csum[v]},  csum monotone (p >= 0), sum(p) ~= 1.
// r <= 0.5: forward scan;  r > 0.5: backward scan with q = 1-r.
// Full chunks (warp-uniform test) use 8 UNGUARDED back-to-back LDG.128 per
// lane -> MLP=8. Partial tail chunk (rarely reached) uses a scalar path.
// Crossing chunk is re-read for the ordered count (guaranteed L2 hit).
// One warp per row, rows distributed via a global atomic counter.
// Output dtype float32 (samples <= 32000 exact in fp32).
// ---------------------------------------------------------------------------
__global__ void __launch_bounds__(256) sampler_kernel(
    const float* __restrict__ p, const float* __restrict__ rng,
    float* __restrict__ out, int V, int rows)
{
    const int lane = threadIdx.x & 31;
    const int nch  = (V + CHUNK - 1) / CHUNK;

    for (;;) {
        int row;
        if (lane == 0) row = atomicAdd(&g_row_counter, 1);
        row = __shfl_sync(0xFFFFFFFFu, row, 0);
        if (row >= rows) return;

        const float r = __ldg(&rng[row]);
        const float* __restrict__ prow = p + (size_t)row * V;
        const bool fwd = (r <= 0.5f);
        const float thr = fwd ? r : (1.0f - r);

        // ---- streaming scan ----
        float acc = 0.0f;        // mass already passed (fwd: prefix; bwd: suffix)
        int   cross = -1;

        for (int c = 0; c < nch; c++) {
            const int lo = fwd ? c * CHUNK : max(0, V - (c + 1) * CHUNK);
            const int hi = fwd ? min(V, (c + 1) * CHUNK) : (V - c * CHUNK);

            float s;
            if (hi - lo == CHUNK) {
                // FAST PATH: 8 unguarded, independent LDG.128 (batched, MLP=8)
                const float* base = prow + lo + lane * 4;
                float4 b0 = *reinterpret_cast<const float4*>(base + 0 * 128);
                float4 b1 = *reinterpret_cast<const float4*>(base + 1 * 128);
                float4 b2 = *reinterpret_cast<const float4*>(base + 2 * 128);
                float4 b3 = *reinterpret_cast<const float4*>(base + 3 * 128);
                float4 b4 = *reinterpret_cast<const float4*>(base + 4 * 128);
                float4 b5 = *reinterpret_cast<const float4*>(base + 5 * 128);
                float4 b6 = *reinterpret_cast<const float4*>(base + 6 * 128);
                float4 b7 = *reinterpret_cast<const float4*>(base + 7 * 128);
                s = (((b0.x + b0.y) + (b0.z + b0.w))
                   + ((b1.x + b1.y) + (b1.z + b1.w)))
                  + (((b2.x + b2.y) + (b2.z + b2.w))
                   + ((b3.x + b3.y) + (b3.z + b3.w)))
                  + (((b4.x + b4.y) + (b4.z + b4.w))
                   + ((b5.x + b5.y) + (b5.z + b5.w)))
                  + (((b6.x + b6.y) + (b6.z + b6.w))
                   + ((b7.x + b7.y) + (b7.z + b7.w)));
            } else {
                // SLOW PATH: partial tail chunk, scalar strided loads
                s = 0.0f;
                for (int i = lo + lane; i < hi; i += 32) s += prow[i];
            }
            #pragma unroll
            for (int d = 16; d > 0; d >>= 1)
                s += __shfl_xor_sync(0xFFFFFFFFu, s, d);

            const bool hit = fwd ? (acc + s >= thr) : (acc + s > thr);
            if (hit) { cross = c; break; }
            acc += s;
        }

        // ---- resolve inside the crossing chunk (re-read: L2 hit) ----
        float res;
        if (cross < 0) {
            res = fwd ? (float)V : 0.0f;   // unreachable in practice (sum ~1)
        } else if (fwd) {
            const int lo = cross * CHUNK;
            const int hi = min(V, lo + CHUNK);
            const bool full = (hi - lo == CHUNK);
            float carry = acc;
            int cnt = 0;
            #pragma unroll
            for (int j = 0; j < NSUB; j++) {
                const int idx = lo + j * 128 + lane * 4;
                float4 a;
                if (full) {
                    a = *reinterpret_cast<const float4*>(prow + idx);
                } else {
                    a = make_float4(0.f, 0.f, 0.f, 0.f);
                    if (idx + 4 <= hi) a = *reinterpret_cast<const float4*>(prow + idx);
                    else {
                        if (idx + 0 < hi) a.x = prow[idx + 0];
                        if (idx + 1 < hi) a.y = prow[idx + 1];
                        if (idx + 2 < hi) a.z = prow[idx + 2];
                    }
                }
                const float s4 = (a.x + a.y) + (a.z + a.w);
                float scan = s4;
                #pragma unroll
                for (int d = 1; d < 32; d <<= 1) {
                    float y = __shfl_up_sync(0xFFFFFFFFu, scan, d);
                    if (lane >= d) scan += y;
                }
                const float c0 = carry + (scan - s4) + a.x;
                const float c1 = c0 + a.y;
                const float c2 = c1 + a.z;
                const float c3 = c2 + a.w;
                cnt += (idx + 0 < hi && c0 < thr);
                cnt += (idx + 1 < hi && c1 < thr);
                cnt += (idx + 2 < hi && c2 < thr);
                cnt += (idx + 3 < hi && c3 < thr);
                carry += __shfl_sync(0xFFFFFFFFu, scan, 31);
            }
            #pragma unroll
            for (int d = 16; d > 0; d >>= 1)
                cnt += __shfl_xor_sync(0xFFFFFFFFu, cnt, d);
            res = (float)(lo + cnt);
        } else {
            // backward: count v in [lo,hi) with suf[v] > q; acc = suffix >= hi
            const int hi = V - cross * CHUNK;
            const int lo = max(0, hi - CHUNK);
            const bool full = (hi - lo == CHUNK);
            float carry = acc;
            int cnt = 0;
            #pragma unroll
            for (int j = NSUB - 1; j >= 0; j--) {
                const int idx = lo + j * 128 + lane * 4;
                float4 a;
                if (full) {
                    a = *reinterpret_cast<const float4*>(prow + idx);
                } else {
                    a = make_float4(0.f, 0.f, 0.f, 0.f);
                    if (idx + 4 <= hi) a = *reinterpret_cast<const float4*>(prow + idx);
                    else {
                        if (idx + 0 < hi) a.x = prow[idx + 0];
                        if (idx + 1 < hi) a.y = prow[idx + 1];
                        if (idx + 2 < hi) a.z = prow[idx + 2];
                    }
                }
                const float s4 = (a.x + a.y) + (a.z + a.w);
                float rs = s4;                      // reverse inclusive scan
                #pragma unroll
                for (int d = 1; d < 32; d <<= 1) {
                    float y = __shfl_down_sync(0xFFFFFFFFu, rs, d);
                    if (lane < 32 - d) rs += y;
                }
                const float rev_excl = rs - s4;
                const float sw = carry + rev_excl + a.w;   // suf[idx+3]
                const float sz = sw + a.z;                 // suf[idx+2]
                const float sy = sz + a.y;                 // suf[idx+1]
                const float sx = sy + a.x;                 // suf[idx]
                cnt += (idx + 3 < hi && sw > thr);
                cnt += (idx + 2 < hi && sz > thr);
                cnt += (idx + 1 < hi && sy > thr);
                cnt += (idx + 0 < hi && sx > thr);
                carry += __shfl_sync(0xFFFFFFFFu, rs, 0);
            }
            #pragma unroll
            for (int d = 16; d > 0; d >>= 1)
                cnt += __shfl_xor_sync(0xFFFFFFFFu, cnt, d);
            res = (float)(lo + cnt - 1 + (acc > thr ? 1 : 0));
        }

        if (lane == 0) out[row] = res;
    }
}

extern "C" void kernel_launch(void* const* d_in, const int* in_sizes, int n_in,
                              void* d_out, int out_size) {
    // Resolve inputs by element count (p is the huge one, rng has `rows`).
    int ip = 0;
    for (int i = 1; i < n_in; i++)
        if (in_sizes[i] > in_sizes[ip]) ip = i;
    const float* p = (const float*)d_in[ip];

    const int rows = out_size;                       // B*T = 8192
    int ir = (ip == 0) ? 1 : 0;
    for (int i = 0; i < n_in; i++)
        if (i != ip && in_sizes[i] == rows) { ir = i; break; }
    const float* rng = (const float*)d_in[ir];

    float* out = (float*)d_out;                      // output dtype: float32

    const long long pelems = (long long)in_sizes[ip];
    const int V = (int)(pelems / rows);              // 32000

    reset_counter_kernel<<<1, 1>>>();
    sampler_kernel<<<1184, 256>>>(p, rng, out, V, rows);
}

// round 10
// speedup vs baseline: 1.0627x; 1.0627x over previous
#include <cuda_runtime.h>
#include <cstdint>

#define CHUNK 1024          // floats per early-exit quantum (4 KB)
#define NSUB  8             // sub-blocks of 128 floats (one float4 per lane)
#define MAXROWS 32768
#define MAXBINS 256

__device__ int g_row_counter;
__device__ int g_cursor[MAXBINS];
__device__ int g_order[MAXROWS];

// ---------------------------------------------------------------------------
// Setup: histogram rows by estimated chunk count (work = min(r,1-r)),
// exclusive-prefix in DESCENDING work order, init cursors + steal counter.
// One CTA; ~8192 elements — negligible.
// ---------------------------------------------------------------------------
__global__ void setup_kernel(const float* __restrict__ rng, int rows, int V, int nch) {
    __shared__ int hist[MAXBINS];
    const int t = threadIdx.x;
    for (int b = t; b < MAXBINS; b += blockDim.x) hist[b] = 0;
    __syncthreads();
    for (int i = t; i < rows; i += blockDim.x) {
        const float r = rng[i];
        const float w = fminf(r, 1.0f - r);
        int est = (int)ceilf(w * (float)V / (float)CHUNK);
        est = max(1, min(est, nch));
        int bin = min(nch - est, MAXBINS - 1);   // bin 0 = longest rows
        atomicAdd(&hist[bin], 1);
    }
    __syncthreads();
    if (t == 0) {
        int acc = 0;
        for (int b = 0; b < MAXBINS; b++) { g_cursor[b] = acc; acc += hist[b]; }
        g_row_counter = 0;
    }
}

// Scatter row ids into work-descending order.
__global__ void scatter_kernel(const float* __restrict__ rng, int rows, int V, int nch) {
    const int i = blockIdx.x * blockDim.x + threadIdx.x;
    if (i >= rows) return;
    const float r = rng[i];
    const float w = fminf(r, 1.0f - r);
    int est = (int)ceilf(w * (float)V / (float)CHUNK);
    est = max(1, min(est, nch));
    int bin = min(nch - est, MAXBINS - 1);
    const int pos = atomicAdd(&g_cursor[bin], 1);
    g_order[pos] = i;
}

// ---------------------------------------------------------------------------
// Warp-autonomous bidirectional inverse-CDF sampler (R6 body).
//   sample = #{v : r > csum[v]},  csum monotone (p >= 0), sum(p) ~= 1.
// r <= 0.5: forward scan;  r > 0.5: backward scan with q = 1-r.
// Chunk data retained in registers (forces batched LDG.128, MLP=8) and
// reused for the ordered in-chunk count on crossing.
// Persistent CTAs; warps steal rows LONGEST-FIRST from g_order.
// Output dtype float32 (samples <= 32000 exact in fp32).
// ---------------------------------------------------------------------------
__global__ void __launch_bounds__(256, 4) sampler_kernel(
    const float* __restrict__ p, const float* __restrict__ rng,
    float* __restrict__ out, int V, int rows)
{
    const int lane = threadIdx.x & 31;
    const int nch  = (V + CHUNK - 1) / CHUNK;

    for (;;) {
        int idx;
        if (lane == 0) idx = atomicAdd(&g_row_counter, 1);
        idx = __shfl_sync(0xFFFFFFFFu, idx, 0);
        if (idx >= rows) return;
        const int row = g_order[idx];

        const float r = __ldg(&rng[row]);
        const float* __restrict__ prow = p + (size_t)row * V;
        const bool fwd = (r <= 0.5f);
        const float thr = fwd ? r : (1.0f - r);   // forward: r;  backward: q

        if (fwd) {
            // ---------------- forward scan ----------------
            float acc = 0.0f;
            float res = (float)V;                  // fallback (sum ~1 > r: unreachable)
            for (int c = 0; c < nch; c++) {
                const int lo = c * CHUNK;
                const int hi = min(V, lo + CHUNK);
                float4 x[NSUB]; float s4[NSUB];
                #pragma unroll
                for (int j = 0; j < NSUB; j++) {
                    const int idx2 = lo + j * 128 + lane * 4;
                    float4 a = make_float4(0.f, 0.f, 0.f, 0.f);
                    if (idx2 + 4 <= hi) {
                        a = *reinterpret_cast<const float4*>(prow + idx2);
                    } else {
                        if (idx2 + 0 < hi) a.x = prow[idx2 + 0];
                        if (idx2 + 1 < hi) a.y = prow[idx2 + 1];
                        if (idx2 + 2 < hi) a.z = prow[idx2 + 2];
                    }
                    x[j]  = a;
                    s4[j] = (a.x + a.y) + (a.z + a.w);
                }
                float tot = ((s4[0] + s4[1]) + (s4[2] + s4[3]))
                          + ((s4[4] + s4[5]) + (s4[6] + s4[7]));
                #pragma unroll
                for (int d = 16; d > 0; d >>= 1)
                    tot += __shfl_xor_sync(0xFFFFFFFFu, tot, d);

                if (acc + tot >= thr) {
                    float carry = acc;
                    int cnt = 0;
                    #pragma unroll
                    for (int j = 0; j < NSUB; j++) {
                        float scan = s4[j];
                        #pragma unroll
                        for (int d = 1; d < 32; d <<= 1) {
                            float y = __shfl_up_sync(0xFFFFFFFFu, scan, d);
                            if (lane >= d) scan += y;
                        }
                        const int idx2 = lo + j * 128 + lane * 4;
                        const float c0 = carry + (scan - s4[j]) + x[j].x;
                        const float c1 = c0 + x[j].y;
                        const float c2 = c1 + x[j].z;
                        const float c3 = c2 + x[j].w;
                        cnt += (idx2 + 0 < hi && c0 < thr);
                        cnt += (idx2 + 1 < hi && c1 < thr);
                        cnt += (idx2 + 2 < hi && c2 < thr);
                        cnt += (idx2 + 3 < hi && c3 < thr);
                        carry += __shfl_sync(0xFFFFFFFFu, scan, 31);
                    }
                    #pragma unroll
                    for (int d = 16; d > 0; d >>= 1)
                        cnt += __shfl_xor_sync(0xFFFFFFFFu, cnt, d);
                    res = (float)(lo + cnt);
                    break;
                }
                acc += tot;
            }
            if (lane == 0) out[row] = res;
        } else {
            // ---------------- backward scan ----------------
            float acc = 0.0f;                      // suffix sum of scanned chunks
            float res = 0.0f;                      // fallback (sum ~1 > q: unreachable)
            for (int c = 0; c < nch; c++) {
                const int hi = V - c * CHUNK;
                const int lo = max(0, hi - CHUNK);
                float4 x[NSUB]; float s4[NSUB];
                #pragma unroll
                for (int j = 0; j < NSUB; j++) {
                    const int idx2 = lo + j * 128 + lane * 4;
                    float4 a = make_float4(0.f, 0.f, 0.f, 0.f);
                    if (idx2 + 4 <= hi) {
                        a = *reinterpret_cast<const float4*>(prow + idx2);
                    } else {
                        if (idx2 + 0 < hi) a.x = prow[idx2 + 0];
                        if (idx2 + 1 < hi) a.y = prow[idx2 + 1];
                        if (idx2 + 2 < hi) a.z = prow[idx2 + 2];
                    }
                    x[j]  = a;
                    s4[j] = (a.x + a.y) + (a.z + a.w);
                }
                float tot = ((s4[0] + s4[1]) + (s4[2] + s4[3]))
                          + ((s4[4] + s4[5]) + (s4[6] + s4[7]));
                #pragma unroll
                for (int d = 16; d > 0; d >>= 1)
                    tot += __shfl_xor_sync(0xFFFFFFFFu, tot, d);

                if (acc + tot > thr) {
                    // count v in [lo,hi) with suf[v] > q; acc = suffix >= hi
                    float carry = acc;
                    int cnt = 0;
                    #pragma unroll
                    for (int j = NSUB - 1; j >= 0; j--) {
                        float rs = s4[j];          // reverse inclusive scan
                        #pragma unroll
                        for (int d = 1; d < 32; d <<= 1) {
                            float y = __shfl_down_sync(0xFFFFFFFFu, rs, d);
                            if (lane < 32 - d) rs += y;
                        }
                        const float rev_excl = rs - s4[j];
                        const int idx2 = lo + j * 128 + lane * 4;
                        const float sw = carry + rev_excl + x[j].w;  // suf[idx2+3]
                        const float sz = sw + x[j].z;                // suf[idx2+2]
                        const float sy = sz + x[j].y;                // suf[idx2+1]
                        const float sx = sy + x[j].x;                // suf[idx2]
                        cnt += (idx2 + 3 < hi && sw > thr);
                        cnt += (idx2 + 2 < hi && sz > thr);
                        cnt += (idx2 + 1 < hi && sy > thr);
                        cnt += (idx2 + 0 < hi && sx > thr);
                        carry += __shfl_sync(0xFFFFFFFFu, rs, 0);
                    }
                    #pragma unroll
                    for (int d = 16; d > 0; d >>= 1)
                        cnt += __shfl_xor_sync(0xFFFFFFFFu, cnt, d);
                    res = (float)(lo + cnt - 1 + (acc > thr ? 1 : 0));
                    break;
                }
                acc += tot;
            }
            if (lane == 0) out[row] = res;
        }
    }
}

extern "C" void kernel_launch(void* const* d_in, const int* in_sizes, int n_in,
                              void* d_out, int out_size) {
    // Resolve inputs by element count (p is the huge one, rng has `rows`).
    int ip = 0;
    for (int i = 1; i < n_in; i++)
        if (in_sizes[i] > in_sizes[ip]) ip = i;
    const float* p = (const float*)d_in[ip];

    const int rows = out_size;                       // B*T = 8192
    int ir = (ip == 0) ? 1 : 0;
    for (int i = 0; i < n_in; i++)
        if (i != ip && in_sizes[i] == rows) { ir = i; break; }
    const float* rng = (const float*)d_in[ir];

    float* out = (float*)d_out;                      // output dtype: float32

    const long long pelems = (long long)in_sizes[ip];
    const int V   = (int)(pelems / rows);            // 32000
    const int nch = (V + CHUNK - 1) / CHUNK;         // 32

    setup_kernel<<<1, 512>>>(rng, rows, V, nch);
    scatter_kernel<<<(rows + 255) / 256, 256>>>(rng, rows, V, nch);
    // one resident wave: 4 CTAs/SM x ~152 SMs
    sampler_kernel<<<608, 256>>>(p, rng, out, V, rows);
}

// round 11
// speedup vs baseline: 1.3141x; 1.2365x over previous
#include <cuda_runtime.h>
#include <cstdint>

#define SEGSZ  1024          // floats per segment (8 float4 per lane)
#define MARGIN 512           // elements of safety on the predicted crossing (~7 sigma)
#define MAXSEG 32            // ceil(32000/1024)

// ---------------------------------------------------------------------------
// Predicted-span inverse-CDF sampler. One CTA (256 thr / 8 warps) per row.
//   sample = #{v : r > csum[v]},  csum monotone (p >= 0), sum(p) ~= 1.
// r <= 0.5: forward;  r > 0.5: backward with q = 1-r (suffix formulation).
// The crossing sits at ~thr*V +- ~75 elements (concentration of normalized
// uniforms), so we read span = thr*V + MARGIN in ONE parallel pass:
//   Phase 1: warps cooperatively compute 1024-float segment sums (8 batched
//            LDG.128 per lane, no serialization) into smem.
//   Phase 2: warp 0 scans the <=32 segment sums, ballot-finds the crossing.
//   Phase 3: warp 0 recounts the crossing segment (just-read => L2 hit).
// If the span misses (astronomically rare), retry with the full direction.
// Output dtype float32 (samples <= 32000 exact in fp32).
// ---------------------------------------------------------------------------
__global__ void __launch_bounds__(256) sampler_kernel(
    const float* __restrict__ p, const float* __restrict__ rng,
    float* __restrict__ out, int V)
{
    const int row  = blockIdx.x;
    const int t    = threadIdx.x;
    const int lane = t & 31;
    const int warp = t >> 5;

    __shared__ float s_seg[MAXSEG];
    __shared__ int   s_cross;
    __shared__ float s_pexcl;

    const float r = __ldg(&rng[row]);
    const float* __restrict__ prow = p + (size_t)row * V;
    const bool  fwd = (r <= 0.5f);
    const float thr = fwd ? r : (1.0f - r);

    const int nseg_total = (V + SEGSZ - 1) / SEGSZ;
    int nseg = (int)((thr * (float)V + (float)MARGIN) * (1.0f / SEGSZ)) + 1;
    if (nseg > nseg_total) nseg = nseg_total;

    for (;;) {
        // ---- Phase 1: parallel segment sums over the span ----
        for (int s = warp; s < nseg; s += 8) {
            int lo, hi;
            if (fwd) { lo = s * SEGSZ; hi = min(V, lo + SEGSZ); }
            else     { hi = V - s * SEGSZ; lo = max(0, hi - SEGSZ); }
            float v;
            if (hi - lo == SEGSZ) {
                const float* base = prow + lo + lane * 4;
                float4 b0 = *reinterpret_cast<const float4*>(base + 0 * 128);
                float4 b1 = *reinterpret_cast<const float4*>(base + 1 * 128);
                float4 b2 = *reinterpret_cast<const float4*>(base + 2 * 128);
                float4 b3 = *reinterpret_cast<const float4*>(base + 3 * 128);
                float4 b4 = *reinterpret_cast<const float4*>(base + 4 * 128);
                float4 b5 = *reinterpret_cast<const float4*>(base + 5 * 128);
                float4 b6 = *reinterpret_cast<const float4*>(base + 6 * 128);
                float4 b7 = *reinterpret_cast<const float4*>(base + 7 * 128);
                v = (((b0.x + b0.y) + (b0.z + b0.w)) + ((b1.x + b1.y) + (b1.z + b1.w)))
                  + (((b2.x + b2.y) + (b2.z + b2.w)) + ((b3.x + b3.y) + (b3.z + b3.w)))
                  + (((b4.x + b4.y) + (b4.z + b4.w)) + ((b5.x + b5.y) + (b5.z + b5.w)))
                  + (((b6.x + b6.y) + (b6.z + b6.w)) + ((b7.x + b7.y) + (b7.z + b7.w)));
            } else {
                v = 0.0f;
                for (int i = lo + lane; i < hi; i += 32) v += prow[i];
            }
            #pragma unroll
            for (int d = 16; d > 0; d >>= 1)
                v += __shfl_xor_sync(0xFFFFFFFFu, v, d);
            if (lane == 0) s_seg[s] = v;
        }
        __syncthreads();

        // ---- Phase 2: warp 0 scans segment sums, finds crossing ----
        if (warp == 0) {
            float x = (lane < nseg) ? s_seg[lane] : 0.0f;
            float incl = x;
            #pragma unroll
            for (int d = 1; d < 32; d <<= 1) {
                float y = __shfl_up_sync(0xFFFFFFFFu, incl, d);
                if (lane >= d) incl += y;
            }
            const bool hit = (lane < nseg) &&
                             (fwd ? (incl >= thr) : (incl > thr));
            const unsigned m = __ballot_sync(0xFFFFFFFFu, hit);
            const int cross = m ? (__ffs(m) - 1) : -1;
            float pexcl = 0.0f;
            if (cross > 0) pexcl = __shfl_sync(0xFFFFFFFFu, incl, cross - 1);
            if (lane == 0) { s_cross = cross; s_pexcl = pexcl; }
        }
        __syncthreads();

        const int cross = s_cross;
        if (cross >= 0) break;
        if (nseg == nseg_total) {                 // mass below thr in the whole
            if (t == 0) out[row] = fwd ? (float)V : 0.0f;  // direction
            return;
        }
        nseg = nseg_total;                        // rare: prediction missed
        __syncthreads();
    }

    // ---- Phase 3: warp 0 recounts inside the crossing segment (L2 hit) ----
    if (warp != 0) return;
    const int cross = s_cross;
    float carry = s_pexcl;                        // fwd: prefix<lo; bwd: suffix>=hi
    int lo, hi;
    if (fwd) { lo = cross * SEGSZ; hi = min(V, lo + SEGSZ); }
    else     { hi = V - cross * SEGSZ; lo = max(0, hi - SEGSZ); }
    int cnt = 0;

    if (fwd) {
        #pragma unroll
        for (int j = 0; j < 8; j++) {
            const int idx = lo + j * 128 + lane * 4;
            float4 a = make_float4(0.f, 0.f, 0.f, 0.f);
            if (idx + 4 <= hi) a = *reinterpret_cast<const float4*>(prow + idx);
            else {
                if (idx + 0 < hi) a.x = prow[idx + 0];
                if (idx + 1 < hi) a.y = prow[idx + 1];
                if (idx + 2 < hi) a.z = prow[idx + 2];
            }
            const float s4 = (a.x + a.y) + (a.z + a.w);
            float scan = s4;
            #pragma unroll
            for (int d = 1; d < 32; d <<= 1) {
                float y = __shfl_up_sync(0xFFFFFFFFu, scan, d);
                if (lane >= d) scan += y;
            }
            const float c0 = carry + (scan - s4) + a.x;
            const float c1 = c0 + a.y;
            const float c2 = c1 + a.z;
            const float c3 = c2 + a.w;
            cnt += (idx + 0 < hi && c0 < thr);
            cnt += (idx + 1 < hi && c1 < thr);
            cnt += (idx + 2 < hi && c2 < thr);
            cnt += (idx + 3 < hi && c3 < thr);
            carry += __shfl_sync(0xFFFFFFFFu, scan, 31);
        }
        #pragma unroll
        for (int d = 16; d > 0; d >>= 1)
            cnt += __shfl_xor_sync(0xFFFFFFFFu, cnt, d);
        if (lane == 0) out[row] = (float)(lo + cnt);
    } else {
        #pragma unroll
        for (int j = 7; j >= 0; j--) {
            const int idx = lo + j * 128 + lane * 4;
            float4 a = make_float4(0.f, 0.f, 0.f, 0.f);
            if (idx + 4 <= hi) a = *reinterpret_cast<const float4*>(prow + idx);
            else {
                if (idx + 0 < hi) a.x = prow[idx + 0];
                if (idx + 1 < hi) a.y = prow[idx + 1];
                if (idx + 2 < hi) a.z = prow[idx + 2];
            }
            const float s4 = (a.x + a.y) + (a.z + a.w);
            float rs = s4;                        // reverse inclusive scan
            #pragma unroll
            for (int d = 1; d < 32; d <<= 1) {
                float y = __shfl_down_sync(0xFFFFFFFFu, rs, d);
                if (lane < 32 - d) rs += y;
            }
            const float rev_excl = rs - s4;
            const float sw = carry + rev_excl + a.w;   // suf[idx+3]
            const float sz = sw + a.z;                 // suf[idx+2]
            const float sy = sz + a.y;                 // suf[idx+1]
            const float sx = sy + a.x;                 // suf[idx]
            cnt += (idx + 3 < hi && sw > thr);
            cnt += (idx + 2 < hi && sz > thr);
            cnt += (idx + 1 < hi && sy > thr);
            cnt += (idx + 0 < hi && sx > thr);
            carry += __shfl_sync(0xFFFFFFFFu, rs, 0);
        }
        #pragma unroll
        for (int d = 16; d > 0; d >>= 1)
            cnt += __shfl_xor_sync(0xFFFFFFFFu, cnt, d);
        if (lane == 0) out[row] = (float)(lo + cnt - 1 + (carry > thr ? 1 : 0));
    }
}

extern "C" void kernel_launch(void* const* d_in, const int* in_sizes, int n_in,
                              void* d_out, int out_size) {
    // Resolve inputs by element count (p is the huge one, rng has `rows`).
    int ip = 0;
    for (int i = 1; i < n_in; i++)
        if (in_sizes[i] > in_sizes[ip]) ip = i;
    const float* p = (const float*)d_in[ip];

    const int rows = out_size;                       // B*T = 8192
    int ir = (ip == 0) ? 1 : 0;
    for (int i = 0; i < n_in; i++)
        if (i != ip && in_sizes[i] == rows) { ir = i; break; }
    const float* rng = (const float*)d_in[ir];

    float* out = (float*)d_out;                      // output dtype: float32

    const long long pelems = (long long)in_sizes[ip];
    const int V = (int)(pelems / rows);              // 32000

    sampler_kernel<<<rows, 256>>>(p, rng, out, V);
}

// round 12
// speedup vs baseline: 1.3149x; 1.0006x over previous
#include <cuda_runtime.h>
#include <cstdint>

#define SEGSZ   1024         // floats per segment (8 float4 per lane)
#define MARGIN  256          // safety on predicted crossing (~3.4 sigma)
#define MAXSEG  32           // ceil(32000/1024)
#define NWARPS  4            // 128-thread CTAs

// ---------------------------------------------------------------------------
// Predicted-span inverse-CDF sampler. One CTA (128 thr / 4 warps) per row.
//   sample = #{v : r > csum[v]},  csum monotone (p >= 0), sum(p) ~= 1.
// r <= 0.5: forward;  r > 0.5: backward with q = 1-r (suffix formulation).
// Crossing concentrates at ~thr*V +- ~75 elems, so read span = thr*V+MARGIN
// in ONE parallel pass (batched LDG.128, no serial chunk loop):
//   Phase 1: warps compute 1024-float segment sums into smem.
//   Phase 2: warp 0 scans <=32 segment sums, ballot-finds the crossing.
//   Phase 3: warp 0 recounts the crossing segment (just read => L2 hit).
// Span miss (rare, ~3e-4/row) retries with the full direction — correct.
// Output dtype float32 (samples <= 32000 exact in fp32).
// ---------------------------------------------------------------------------
__global__ void __launch_bounds__(128) sampler_kernel(
    const float* __restrict__ p, const float* __restrict__ rng,
    float* __restrict__ out, int V)
{
    const int row  = blockIdx.x;
    const int t    = threadIdx.x;
    const int lane = t & 31;
    const int warp = t >> 5;

    __shared__ float s_seg[MAXSEG];
    __shared__ int   s_cross;
    __shared__ float s_pexcl;

    const float r = __ldg(&rng[row]);
    const float* __restrict__ prow = p + (size_t)row * V;
    const bool  fwd = (r <= 0.5f);
    const float thr = fwd ? r : (1.0f - r);

    const int nseg_total = (V + SEGSZ - 1) / SEGSZ;
    int nseg = (int)((thr * (float)V + (float)MARGIN) * (1.0f / SEGSZ)) + 1;
    if (nseg > nseg_total) nseg = nseg_total;

    for (;;) {
        // ---- Phase 1: parallel segment sums over the span ----
        for (int s = warp; s < nseg; s += NWARPS) {
            int lo, hi;
            if (fwd) { lo = s * SEGSZ; hi = min(V, lo + SEGSZ); }
            else     { hi = V - s * SEGSZ; lo = max(0, hi - SEGSZ); }
            float v;
            if (hi - lo == SEGSZ) {
                const float* base = prow + lo + lane * 4;
                float4 b0 = *reinterpret_cast<const float4*>(base + 0 * 128);
                float4 b1 = *reinterpret_cast<const float4*>(base + 1 * 128);
                float4 b2 = *reinterpret_cast<const float4*>(base + 2 * 128);
                float4 b3 = *reinterpret_cast<const float4*>(base + 3 * 128);
                float4 b4 = *reinterpret_cast<const float4*>(base + 4 * 128);
                float4 b5 = *reinterpret_cast<const float4*>(base + 5 * 128);
                float4 b6 = *reinterpret_cast<const float4*>(base + 6 * 128);
                float4 b7 = *reinterpret_cast<const float4*>(base + 7 * 128);
                v = (((b0.x + b0.y) + (b0.z + b0.w)) + ((b1.x + b1.y) + (b1.z + b1.w)))
                  + (((b2.x + b2.y) + (b2.z + b2.w)) + ((b3.x + b3.y) + (b3.z + b3.w)))
                  + (((b4.x + b4.y) + (b4.z + b4.w)) + ((b5.x + b5.y) + (b5.z + b5.w)))
                  + (((b6.x + b6.y) + (b6.z + b6.w)) + ((b7.x + b7.y) + (b7.z + b7.w)));
            } else {
                v = 0.0f;
                for (int i = lo + lane; i < hi; i += 32) v += prow[i];
            }
            #pragma unroll
            for (int d = 16; d > 0; d >>= 1)
                v += __shfl_xor_sync(0xFFFFFFFFu, v, d);
            if (lane == 0) s_seg[s] = v;
        }
        __syncthreads();

        // ---- Phase 2: warp 0 scans segment sums, finds crossing ----
        if (warp == 0) {
            float x = (lane < nseg) ? s_seg[lane] : 0.0f;
            float incl = x;
            #pragma unroll
            for (int d = 1; d < 32; d <<= 1) {
                float y = __shfl_up_sync(0xFFFFFFFFu, incl, d);
                if (lane >= d) incl += y;
            }
            const bool hit = (lane < nseg) &&
                             (fwd ? (incl >= thr) : (incl > thr));
            const unsigned m = __ballot_sync(0xFFFFFFFFu, hit);
            const int cross = m ? (__ffs(m) - 1) : -1;
            float pexcl = 0.0f;
            if (cross > 0) pexcl = __shfl_sync(0xFFFFFFFFu, incl, cross - 1);
            if (lane == 0) { s_cross = cross; s_pexcl = pexcl; }
        }
        __syncthreads();

        const int cross = s_cross;
        if (cross >= 0) break;
        if (nseg == nseg_total) {                  // whole direction below thr
            if (t == 0) out[row] = fwd ? (float)V : 0.0f;
            return;
        }
        nseg = nseg_total;                         // rare: prediction missed
        __syncthreads();
    }

    // ---- Phase 3: warp 0 recounts inside the crossing segment (L2 hit) ----
    if (warp != 0) return;
    const int cross = s_cross;
    float carry = s_pexcl;                         // fwd: prefix<lo; bwd: suffix>=hi
    int lo, hi;
    if (fwd) { lo = cross * SEGSZ; hi = min(V, lo + SEGSZ); }
    else     { hi = V - cross * SEGSZ; lo = max(0, hi - SEGSZ); }
    int cnt = 0;

    if (fwd) {
        #pragma unroll
        for (int j = 0; j < 8; j++) {
            const int idx = lo + j * 128 + lane * 4;
            float4 a = make_float4(0.f, 0.f, 0.f, 0.f);
            if (idx + 4 <= hi) a = *reinterpret_cast<const float4*>(prow + idx);
            else {
                if (idx + 0 < hi) a.x = prow[idx + 0];
                if (idx + 1 < hi) a.y = prow[idx + 1];
                if (idx + 2 < hi) a.z = prow[idx + 2];
            }
            const float s4 = (a.x + a.y) + (a.z + a.w);
            float scan = s4;
            #pragma unroll
            for (int d = 1; d < 32; d <<= 1) {
                float y = __shfl_up_sync(0xFFFFFFFFu, scan, d);
                if (lane >= d) scan += y;
            }
            const float c0 = carry + (scan - s4) + a.x;
            const float c1 = c0 + a.y;
            const float c2 = c1 + a.z;
            const float c3 = c2 + a.w;
            cnt += (idx + 0 < hi && c0 < thr);
            cnt += (idx + 1 < hi && c1 < thr);
            cnt += (idx + 2 < hi && c2 < thr);
            cnt += (idx + 3 < hi && c3 < thr);
            carry += __shfl_sync(0xFFFFFFFFu, scan, 31);
        }
        #pragma unroll
        for (int d = 16; d > 0; d >>= 1)
            cnt += __shfl_xor_sync(0xFFFFFFFFu, cnt, d);
        if (lane == 0) out[row] = (float)(lo + cnt);
    } else {
        #pragma unroll
        for (int j = 7; j >= 0; j--) {
            const int idx = lo + j * 128 + lane * 4;
            float4 a = make_float4(0.f, 0.f, 0.f, 0.f);
            if (idx + 4 <= hi) a = *reinterpret_cast<const float4*>(prow + idx);
            else {
                if (idx + 0 < hi) a.x = prow[idx + 0];
                if (idx + 1 < hi) a.y = prow[idx + 1];
                if (idx + 2 < hi) a.z = prow[idx + 2];
            }
            const float s4 = (a.x + a.y) + (a.z + a.w);
            float rs = s4;                         // reverse inclusive scan
            #pragma unroll
            for (int d = 1; d < 32; d <<= 1) {
                float y = __shfl_down_sync(0xFFFFFFFFu, rs, d);
                if (lane < 32 - d) rs += y;
            }
            const float rev_excl = rs - s4;
            const float sw = carry + rev_excl + a.w;   // suf[idx+3]
            const float sz = sw + a.z;                 // suf[idx+2]
            const float sy = sz + a.y;                 // suf[idx+1]
            const float sx = sy + a.x;                 // suf[idx]
            cnt += (idx + 3 < hi && sw > thr);
            cnt += (idx + 2 < hi && sz > thr);
            cnt += (idx + 1 < hi && sy > thr);
            cnt += (idx + 0 < hi && sx > thr);
            carry += __shfl_sync(0xFFFFFFFFu, rs, 0);
        }
        #pragma unroll
        for (int d = 16; d > 0; d >>= 1)
            cnt += __shfl_xor_sync(0xFFFFFFFFu, cnt, d);
        if (lane == 0) out[row] = (float)(lo + cnt - 1 + (carry > thr ? 1 : 0));
    }
}

extern "C" void kernel_launch(void* const* d_in, const int* in_sizes, int n_in,
                              void* d_out, int out_size) {
    // Resolve inputs by element count (p is the huge one, rng has `rows`).
    int ip = 0;
    for (int i = 1; i < n_in; i++)
        if (in_sizes[i] > in_sizes[ip]) ip = i;
    const float* p = (const float*)d_in[ip];

    const int rows = out_size;                       // B*T = 8192
    int ir = (ip == 0) ? 1 : 0;
    for (int i = 0; i < n_in; i++)
        if (i != ip && in_sizes[i] == rows) { ir = i; break; }
    const float* rng = (const float*)d_in[ir];

    float* out = (float*)d_out;                      // output dtype: float32

    const long long pelems = (long long)in_sizes[ip];
    const int V = (int)(pelems / rows);              // 32000

    sampler_kernel<<<rows, 128>>>(p, rng, out, V);
}